// round 15
// baseline (speedup 1.0000x reference)
#include <cuda_runtime.h>
#include <cuda_fp16.h>
#include <math.h>
#include <cstdint>

#define Bz   64
#define Tz   2048
#define IND  256
#define ST   512
#define OD   256
#define M_ROWS (Bz*Tz)   // 131072
#define EPSC 1e-5f

// ---------------- scratch (static device memory) -----------------------------
__device__ __half g_xh[(size_t)M_ROWS*IND];
__device__ __half g_vh[(size_t)M_ROWS*ST];
__device__ __half g_vch[(size_t)M_ROWS*ST];
__device__ float  g_u [(size_t)M_ROWS*ST];
__device__ __half g_sh[(size_t)M_ROWS*ST];
__device__ __half g_wt[ST*IND];      // W_in  Bt[n][k]
__device__ __half g_wk[ST*3*ST];     // conv  Bt[n][tap*512+i]
__device__ __half g_bm[ST*ST];       // BN-folded Bm, Bt[j][i]
__device__ __half g_ct[OD*ST];       // C     Bt[n][k]
__device__ float g_ubias[ST];
__device__ float g_sum[ST];
__device__ float g_sumsq[ST];

__device__ __forceinline__ uint32_t smem_u32(const void* p) {
    return (uint32_t)__cvta_generic_to_shared(p);
}

// packed f32x2 helpers
__device__ __forceinline__ double pack2(float lo, float hi) {
    double d;
    asm("mov.b64 %0, {%1, %2};" : "=d"(d) : "f"(lo), "f"(hi));
    return d;
}
__device__ __forceinline__ double splat2(float v) {
    double d;
    asm("mov.b64 %0, {%1, %1};" : "=d"(d) : "f"(v));
    return d;
}
__device__ __forceinline__ void unpack2(double d, float& lo, float& hi) {
    asm("mov.b64 {%0, %1}, %2;" : "=f"(lo), "=f"(hi) : "d"(d));
}
__device__ __forceinline__ void fma2(double& acc, double a, double b) {
    asm("fma.rn.f32x2 %0, %1, %2, %0;" : "+d"(acc) : "d"(a), "d"(b));
}

// ---------------- prep: weights -> fp16 ---------------------------------------
__global__ void k_prep(const float* __restrict__ W_in, const float* __restrict__ conv_w,
                       const float* __restrict__ C) {
    int idx = blockIdx.x * blockDim.x + threadIdx.x;
    if (idx < ST*IND) {
        g_wt[idx] = __float2half_rn(W_in[idx]);
    }
    if (idx < ST*3*ST) {
        int n = idx / (3*ST);
        int rem = idx % (3*ST);
        int tap = rem / ST, i = rem % ST;
        g_wk[idx] = __float2half_rn(conv_w[((size_t)n*ST + i)*3 + tap]);
    }
    if (idx < OD*ST) {
        int n = idx / ST, k = idx % ST;
        g_ct[idx] = __float2half_rn(C[(size_t)k*OD + n]);
    }
    if (idx < ST) { g_sum[idx] = 0.f; g_sumsq[idx] = 0.f; }
}

// x -> fp16
__global__ __launch_bounds__(256)
void k_split(const float* __restrict__ x) {
    const size_t i = ((size_t)blockIdx.x * 256 + threadIdx.x) * 4;
    float4 v = *(const float4*)(x + i);
    __half2 h0 = __floats2half2_rn(v.x, v.y);
    __half2 h1 = __floats2half2_rn(v.z, v.w);
    uint2 hh; hh.x = *(uint32_t*)&h0; hh.y = *(uint32_t*)&h1;
    *(uint2*)(g_xh + i) = hh;
}

// ---------------- mma.sync helpers --------------------------------------------
__device__ __forceinline__ void mma16816(float* c, const uint32_t* a, const uint32_t* b) {
    asm volatile(
        "mma.sync.aligned.m16n8k16.row.col.f32.f16.f16.f32 "
        "{%0,%1,%2,%3}, {%4,%5,%6,%7}, {%8,%9}, {%0,%1,%2,%3};"
        : "+f"(c[0]), "+f"(c[1]), "+f"(c[2]), "+f"(c[3])
        : "r"(a[0]), "r"(a[1]), "r"(a[2]), "r"(a[3]), "r"(b[0]), "r"(b[1]));
}
__device__ __forceinline__ void ldsm4(uint32_t* r, uint32_t addr) {
    asm volatile("ldmatrix.sync.aligned.m8n8.x4.shared.b16 {%0,%1,%2,%3}, [%4];"
                 : "=r"(r[0]), "=r"(r[1]), "=r"(r[2]), "=r"(r[3]) : "r"(addr));
}
__device__ __forceinline__ void cpa16(uint32_t dst, const void* src, bool pred) {
    int sz = pred ? 16 : 0;
    asm volatile("cp.async.cg.shared.global [%0], [%1], 16, %2;"
                 :: "r"(dst), "l"(src), "r"(sz) : "memory");
}
#define CPA_COMMIT() asm volatile("cp.async.commit_group;" ::: "memory")

// ---------------- fp16 warp-MMA GEMM (single-term A) ---------------------------
#define SRS 72
#define TILE_HALFS (128*SRS)             // 18432 B
#define CHUNKH (2*TILE_HALFS)            // A, B
#define SMB_TOTAL (3*CHUNKH*2)           // 110592 B

__global__ __launch_bounds__(256, 2)
void k_tgemm(const __half* __restrict__ Ah, const __half* __restrict__ Bp,
             const float* __restrict__ bias, float* __restrict__ outf,
             __half* __restrict__ outh,
             int Kd, int N, int act, int convmode) {
    extern __shared__ __half smem[];
    const int t = threadIdx.x;
    const int w = t >> 5, lane = t & 31;
    const int wm = w >> 1, wn = w & 1;
    const int m0 = blockIdx.y * 128, n0 = blockIdx.x * 128;

    float acc[2][8][4];
#pragma unroll
    for (int i = 0; i < 2; i++)
#pragma unroll
        for (int j = 0; j < 8; j++)
#pragma unroll
            for (int q = 0; q < 4; q++) acc[i][j][q] = 0.f;

    const uint32_t smb = smem_u32(smem);
    const uint32_t aBase = smb +
        (uint32_t)(((wm*32 + (lane & 15)) * SRS + (lane >> 4) * 8) * 2);
    const uint32_t bBase = smb + TILE_HALFS*2 +
        (uint32_t)(((wn*64 + (lane & 7) + ((lane >> 4) & 1) * 8) * SRS
                    + ((lane >> 3) & 1) * 8) * 2);

    const int sr = t >> 3, sj = t & 7;
    const int nch = Kd >> 6;

    auto stage = [&](int c, int buf) {
        const int k0 = c << 6;
        __half* base = smem + buf * CHUNKH;
        __half* sAh = base;
        __half* sB  = base + TILE_HALFS;
        const int tap = convmode ? (k0 >> 9) : 0;
        const int kl0 = convmode ? (k0 & 511) : k0;
#pragma unroll
        for (int it = 0; it < 4; it++) {
            const int r = sr + it * 32;
            const uint32_t so = (uint32_t)((r * SRS + sj * 8) * 2);
            {
                const size_t goff = (size_t)(n0 + r) * Kd + k0 + sj * 8;
                cpa16(smem_u32(sB) + so, Bp + goff, true);
            }
            {
                const int rg = m0 + r;
                bool pred = true;
                size_t goff;
                if (convmode) {
                    const int tl = (rg & (Tz - 1)) + tap - 1;
                    pred = (tl >= 0) && (tl < Tz);
                    const int rs = pred ? (rg + tap - 1) : rg;
                    goff = (size_t)rs * ST + kl0 + sj * 8;
                } else {
                    goff = (size_t)rg * Kd + k0 + sj * 8;
                }
                cpa16(smem_u32(sAh) + so, Ah + goff, pred);
            }
        }
    };

    uint32_t fah[2][4], fb[4][4];

    stage(0, 0);
    CPA_COMMIT();
    if (nch > 1) { stage(1, 1); CPA_COMMIT(); }

    for (int c = 0; c < nch; c++) {
        if (c < nch - 1) asm volatile("cp.async.wait_group 1;" ::: "memory");
        else             asm volatile("cp.async.wait_group 0;" ::: "memory");
        __syncthreads();
        if (c + 2 < nch) { stage(c + 2, (c + 2) % 3); CPA_COMMIT(); }

        const uint32_t boff = (uint32_t)((c % 3) * CHUNKH * 2);
#pragma unroll
        for (int ks = 0; ks < 4; ks++) {
            const uint32_t koff = boff + (uint32_t)(ks * 32);
#pragma unroll
            for (int mi = 0; mi < 2; mi++)
                ldsm4(fah[mi], aBase + (uint32_t)(mi * 16 * SRS * 2) + koff);
#pragma unroll
            for (int nb = 0; nb < 4; nb++)
                ldsm4(fb[nb], bBase + (uint32_t)(nb * 16 * SRS * 2) + koff);
#pragma unroll
            for (int mi = 0; mi < 2; mi++)
#pragma unroll
                for (int ni = 0; ni < 8; ni++)
                    mma16816(acc[mi][ni], fah[mi], &fb[ni >> 1][(ni & 1) * 2]);
        }
    }

    const int g = lane >> 2, tg = lane & 3;
#pragma unroll
    for (int mi = 0; mi < 2; mi++) {
#pragma unroll
        for (int ni = 0; ni < 8; ni++) {
            const int col = n0 + wn*64 + ni*8 + tg*2;
            const float b0 = bias ? bias[col]     : 0.f;
            const float b1 = bias ? bias[col + 1] : 0.f;
#pragma unroll
            for (int half = 0; half < 2; half++) {
                const int row = m0 + wm*32 + mi*16 + g + half*8;
                float v0 = acc[mi][ni][half*2+0] + b0;
                float v1 = acc[mi][ni][half*2+1] + b1;
                if (act == 1) {
                    v0 = v0 / (1.f + expf(-v0));
                    v1 = v1 / (1.f + expf(-v1));
                }
                if (outf) {
                    float2 f2; f2.x = v0; f2.y = v1;
                    *(float2*)(outf + (size_t)row * N + col) = f2;
                }
                if (outh) {
                    __half2 h2 = __floats2half2_rn(v0, v1);
                    *(__half2*)(outh + (size_t)row * N + col) = h2;
                }
            }
        }
    }
}

// ---------------- BN stats -----------------------------------------------------
__global__ __launch_bounds__(512)
void k_stats() {
    const int n = threadIdx.x;
    const int rpc = M_ROWS / 512;
    const int r0 = blockIdx.x * rpc;
    float s1 = 0.f, s2 = 0.f;
    for (int r = 0; r < rpc; r++) {
        const size_t o = (size_t)(r0 + r) * ST + n;
        float v = __half2float(g_vch[o]);
        s1 += v; s2 += v * v;
    }
    atomicAdd(&g_sum[n], s1);
    atomicAdd(&g_sumsq[n], s2);
}

__global__ __launch_bounds__(512)
void k_finalize(const float* __restrict__ Bm, const float* __restrict__ bng,
                const float* __restrict__ bnb) {
    __shared__ float sc[ST], sh[ST];
    const int j = threadIdx.x;
    float mu  = g_sum[j]   * (1.f / M_ROWS);
    float var = g_sumsq[j] * (1.f / M_ROWS) - mu * mu;
    float inv = rsqrtf(var + EPSC);
    float s   = bng[j] * inv;
    sc[j] = s;
    sh[j] = bnb[j] - mu * s;
    __syncthreads();
    float ub = 0.f;
    for (int i = 0; i < ST; i++) {
        float bmv = Bm[(size_t)i * ST + j];
        g_bm[(size_t)j * ST + i] = __float2half_rn(sc[i] * bmv);
        ub += sh[i] * bmv;
    }
    g_ubias[j] = ub;
}

// ---------------- cluster recurrence: f32x2 matvec, 1 sync + 1 barrier/step ----
// sbuf layout: [2][i(512)][chain(4)] -> one LDS.128 gives all 4 chains at i.
// pbuf: [2][rank(8)][16] = per-warp (s1,s2) partials, uncombined.
#define PRED_STRIDE 260
#define RC_OFF_SBUF 32768                            // 4096 floats
#define RC_OFF_PBUF (RC_OFF_SBUF + 4096)             // 256 floats
#define RC_OFF_PRED (RC_OFF_PBUF + 256)              // [32][260]
#define RC_OFF_CS   (RC_OFF_PRED + 32*PRED_STRIDE)   // colsum [64]
#define RC_OFF_CB   (RC_OFF_CS + 64)                 // cbias  [64]
#define RC_SMEM_FLOATS (RC_OFF_CB + 64 + 8)
__global__ __launch_bounds__(512, 1) __cluster_dims__(8, 1, 1)
void k_recur(const float* __restrict__ A, const float* __restrict__ lng,
             const float* __restrict__ lnb) {
    extern __shared__ float sm[];
    float* Atile  = sm;                  // [512][64] = gamma[i]*A[i][jg0+j]
    float* sbuf   = sm + RC_OFF_SBUF;
    float* pbuf   = sm + RC_OFF_PBUF;
    float* pred   = sm + RC_OFF_PRED;
    float* colsum = sm + RC_OFF_CS;
    float* cbias  = sm + RC_OFF_CB;

    const int t    = threadIdx.x;
    const int rank = blockIdx.x;
    const int grp  = blockIdx.y;
    const int jg0  = rank * 64;

    for (int idx = t; idx < 512 * 16; idx += 512) {
        int i  = idx >> 4;
        int jv = (idx & 15) << 2;
        float gi = lng[i];
        float4 a = *(const float4*)(A + (size_t)i*ST + jg0 + jv);
        a.x *= gi; a.y *= gi; a.z *= gi; a.w *= gi;
        *(float4*)&Atile[i*64 + jv] = a;
    }
    for (int idx = t; idx < 4096; idx += 512) sbuf[idx] = 0.f;
    __syncthreads();
    if (t < 64) {
        float cs = 0.f;
        for (int i = 0; i < 512; i++) cs += Atile[i*64 + t];
        colsum[t] = cs;
    } else if (t < 128) {
        const int jj2 = t - 64;
        float cb = 0.f;
        for (int i = 0; i < 512; i++)
            cb += lnb[i] * A[(size_t)i*ST + jg0 + jj2];
        cbias[jj2] = cb;
    }

    const int ip = t >> 4;         // 0..31
    const int jq = t & 15;         // 0..15
    const int c2 = t >> 6;         // chain (t<256)
    const int jj = t & 63;
    const int wid = t >> 5;

    float gj = 0.f, bj = 0.f;
    size_t urow0 = 0;
    if (t < 256) {
        gj = lng[jg0 + jj];
        bj = lnb[jg0 + jj];
        const int chain = grp * 4 + c2;
        urow0 = (size_t)chain * Tz * ST + jg0 + jj;
    }

    const uint32_t sb_base = smem_u32(sbuf);
    const uint32_t pb_base = smem_u32(pbuf);

    __syncthreads();
    asm volatile("barrier.cluster.arrive.aligned;\n" ::: "memory");
    asm volatile("barrier.cluster.wait.aligned;\n" ::: "memory");

    int p = 0;
    float uval  = (t < 256) ? g_u[urow0] : 0.f;
    float yprev = 0.f;

    for (int step = 0; step < Tz; step++) {
        // ---- matvec: packed f32x2 over chain pairs ------------------------
        const float* Arow = Atile + (ip*16)*64 + jq*4;
        const float* sp   = sbuf + p*2048 + (ip*16)*4;
        double acc01[4], acc23[4];
        const double dz = pack2(0.f, 0.f);
#pragma unroll
        for (int j = 0; j < 4; j++) { acc01[j] = dz; acc23[j] = dz; }
#pragma unroll
        for (int ii = 0; ii < 16; ii++) {
            float4 s4 = *(const float4*)(sp + ii*4);
            const double s01 = pack2(s4.x, s4.y);
            const double s23 = pack2(s4.z, s4.w);
            float4 av = *(const float4*)(Arow + ii*64);
            double pa;
            pa = splat2(av.x); fma2(acc01[0], s01, pa); fma2(acc23[0], s23, pa);
            pa = splat2(av.y); fma2(acc01[1], s01, pa); fma2(acc23[1], s23, pa);
            pa = splat2(av.z); fma2(acc01[2], s01, pa); fma2(acc23[2], s23, pa);
            pa = splat2(av.w); fma2(acc01[3], s01, pa); fma2(acc23[3], s23, pa);
        }
        {
            float c0[4], c1[4], c2v[4], c3[4];
#pragma unroll
            for (int j = 0; j < 4; j++) {
                unpack2(acc01[j], c0[j], c1[j]);
                unpack2(acc23[j], c2v[j], c3[j]);
            }
            float* pr = pred + ip * PRED_STRIDE + jq * 4;
            *(float4*)(pr + 0*64) = *(float4*)c0;
            *(float4*)(pr + 1*64) = *(float4*)c1;
            *(float4*)(pr + 2*64) = *(float4*)c2v;
            *(float4*)(pr + 3*64) = *(float4*)c3;
        }
        __syncthreads();

        // ---- finalize (t<256): stats of r_{t-1}, write s_{t-1}, r_t --------
        float ynew = 0.f;
        if (t < 256) {
            float alpha = 0.f, beta = 0.f, cw = 0.f;
            if (step > 0) {
                float q1 = 0.f, q2s = 0.f;
                const int w0 = (c2 << 1) << 1;       // warp 2*c2 -> slot 4*c2
#pragma unroll
                for (int r = 0; r < 8; r++) {
                    const float* pb = pbuf + p*128 + r*16 + w0;
                    q1  += pb[0] + pb[2];
                    q2s += pb[1] + pb[3];
                }
                const float mean = q1 * (1.f / ST);
                const float var  = q2s * (1.f / ST) - mean * mean;
                const float rstd = rsqrtf(var + EPSC);
                alpha = rstd; beta = -rstd * mean; cw = 1.f;
                const float sv = (yprev - mean) * rstd * gj + bj;
                g_sh[urow0 + (size_t)(step-1) * ST] = __float2half_rn(sv);
            }
            float acc = 0.f;
            const float* pr = pred + c2 * 64 + jj;
#pragma unroll 8
            for (int q = 0; q < 32; q++)
                acc += pr[q * PRED_STRIDE];
            ynew = fmaf(alpha, acc, fmaf(beta, colsum[jj], fmaf(cw, cbias[jj], uval)));

            // broadcast raw r_t to all 8 CTAs: sbuf[p^1][jg0+jj][c2]
            {
                const uint32_t la = sb_base +
                    (uint32_t)((((p^1)*2048) + (jg0 + jj)*4 + c2) * 4);
#pragma unroll
                for (int r = 0; r < 8; r++) {
                    uint32_t ra_;
                    asm volatile("mapa.shared::cluster.u32 %0, %1, %2;" : "=r"(ra_) : "r"(la), "r"(r));
                    asm volatile("st.shared::cluster.f32 [%0], %1;" :: "r"(ra_), "f"(ynew) : "memory");
                }
            }
            // warp-level LN partials, leaders push uncombined
            float s1 = ynew, s2 = ynew * ynew;
#pragma unroll
            for (int o = 16; o > 0; o >>= 1) {
                s1 += __shfl_xor_sync(0xffffffffu, s1, o);
                s2 += __shfl_xor_sync(0xffffffffu, s2, o);
            }
            if ((t & 31) == 0) {
                double pv = pack2(s1, s2);
                const uint32_t la = pb_base +
                    (uint32_t)(((p^1)*128 + rank*16 + wid*2) * 4);
#pragma unroll
                for (int r = 0; r < 8; r++) {
                    uint32_t ra_;
                    asm volatile("mapa.shared::cluster.u32 %0, %1, %2;" : "=r"(ra_) : "r"(la), "r"(r));
                    asm volatile("st.shared::cluster.b64 [%0], %1;" :: "r"(ra_), "d"(pv) : "memory");
                }
            }
        }
        float unext = 0.f;
        if (t < 256 && step + 1 < Tz)
            unext = g_u[urow0 + (size_t)(step + 1) * ST];

        asm volatile("barrier.cluster.arrive.aligned;\n" ::: "memory");
        asm volatile("barrier.cluster.wait.aligned;\n" ::: "memory");

        yprev = ynew;
        uval  = unext;
        p ^= 1;
    }

    // tail: write s_{Tz-1}
    if (t < 256) {
        float q1 = 0.f, q2s = 0.f;
        const int w0 = (c2 << 1) << 1;
#pragma unroll
        for (int r = 0; r < 8; r++) {
            const float* pb = pbuf + p*128 + r*16 + w0;
            q1  += pb[0] + pb[2];
            q2s += pb[1] + pb[3];
        }
        const float mean = q1 * (1.f / ST);
        const float var  = q2s * (1.f / ST) - mean * mean;
        const float rstd = rsqrtf(var + EPSC);
        const float sv = (yprev - mean) * rstd * gj + bj;
        g_sh[urow0 + (size_t)(Tz-1) * ST] = __float2half_rn(sv);
    }
}

// ---------------- launch ------------------------------------------------------
extern "C" void kernel_launch(void* const* d_in, const int* in_sizes, int n_in,
                              void* d_out, int out_size) {
    const float* x      = (const float*)d_in[0];
    const float* W_in   = (const float*)d_in[1];
    const float* b_in   = (const float*)d_in[2];
    const float* conv_w = (const float*)d_in[3];
    const float* conv_b = (const float*)d_in[4];
    const float* bng    = (const float*)d_in[5];
    const float* bnb    = (const float*)d_in[6];
    const float* lng    = (const float*)d_in[7];
    const float* lnb    = (const float*)d_in[8];
    const float* A      = (const float*)d_in[9];
    const float* Bm     = (const float*)d_in[10];
    const float* C      = (const float*)d_in[11];
    float* out = (float*)d_out;

    void *p_xh, *p_vh, *p_vch, *p_u, *p_sh;
    void *p_wt, *p_wk, *p_bm, *p_ct, *p_ub;
    cudaGetSymbolAddress(&p_xh,  g_xh);
    cudaGetSymbolAddress(&p_vh,  g_vh);
    cudaGetSymbolAddress(&p_vch, g_vch);
    cudaGetSymbolAddress(&p_u,   g_u);
    cudaGetSymbolAddress(&p_sh,  g_sh);
    cudaGetSymbolAddress(&p_wt,  g_wt);  cudaGetSymbolAddress(&p_wk,  g_wk);
    cudaGetSymbolAddress(&p_bm,  g_bm);  cudaGetSymbolAddress(&p_ct,  g_ct);
    cudaGetSymbolAddress(&p_ub,  g_ubias);

    cudaFuncSetAttribute(k_tgemm, cudaFuncAttributeMaxDynamicSharedMemorySize, SMB_TOTAL);
    cudaFuncSetAttribute(k_recur, cudaFuncAttributeMaxDynamicSharedMemorySize,
                         RC_SMEM_FLOATS * 4);

    // 1) weights + x -> fp16
    k_prep<<<1536, 512>>>(W_in, conv_w, C);
    k_split<<<(M_ROWS*IND)/1024, 256>>>(x);
    // 2) v = silu(x @ W_in^T + b_in) -> fp16
    k_tgemm<<<dim3(4, 1024), 256, SMB_TOTAL>>>(
        (const __half*)p_xh, (const __half*)p_wt,
        b_in, nullptr, (__half*)p_vh, IND, ST, 1, 0);
    // 3) vc = conv1d(v) + conv_b -> fp16
    k_tgemm<<<dim3(4, 1024), 256, SMB_TOTAL>>>(
        (const __half*)p_vh, (const __half*)p_wk,
        conv_b, nullptr, (__half*)p_vch, 3*ST, ST, 0, 1);
    // 4) BN stats
    k_stats<<<512, 512>>>();
    // 5) fold BN into Bm
    k_finalize<<<1, 512>>>(Bm, bng, bnb);
    // 6) u = vc @ Bm2 + ubias -> fp32
    k_tgemm<<<dim3(4, 1024), 256, SMB_TOTAL>>>(
        (const __half*)p_vch, (const __half*)p_bm,
        (const float*)p_ub, (float*)p_u, nullptr, ST, ST, 0, 0);
    // 7) recurrence (f32x2, 1 sync + 1 barrier per step) -> fp16 states
    k_recur<<<dim3(8, 16), 512, RC_SMEM_FLOATS * 4>>>(A, lng, lnb);
    // 8) y = S @ C
    k_tgemm<<<dim3(2, 1024), 256, SMB_TOTAL>>>(
        (const __half*)p_sh, (const __half*)p_ct,
        nullptr, out, nullptr, ST, OD, 0, 0);
}

// round 16
// speedup vs baseline: 1.4349x; 1.4349x over previous
#include <cuda_runtime.h>
#include <cuda_fp16.h>
#include <math.h>
#include <cstdint>

#define Bz   64
#define Tz   2048
#define IND  256
#define ST   512
#define OD   256
#define M_ROWS (Bz*Tz)   // 131072
#define EPSC 1e-5f

// ---------------- scratch (static device memory) -----------------------------
__device__ __half g_xh[(size_t)M_ROWS*IND];
__device__ __half g_vh[(size_t)M_ROWS*ST];
__device__ __half g_vch[(size_t)M_ROWS*ST];
__device__ float  g_u [(size_t)M_ROWS*ST];
__device__ __half g_sh[(size_t)M_ROWS*ST];
__device__ __half g_wt[ST*IND];      // W_in  Bt[n][k]
__device__ __half g_wk[ST*3*ST];     // conv  Bt[n][tap*512+i]
__device__ __half g_bm[ST*ST];       // BN-folded Bm, Bt[j][i]
__device__ __half g_ct[OD*ST];       // C     Bt[n][k]
__device__ float g_ubias[ST];
__device__ float g_sum[ST];
__device__ float g_sumsq[ST];

__device__ __forceinline__ uint32_t smem_u32(const void* p) {
    return (uint32_t)__cvta_generic_to_shared(p);
}
__device__ __forceinline__ double pack2(float lo, float hi) {
    double d;
    asm("mov.b64 %0, {%1, %2};" : "=d"(d) : "f"(lo), "f"(hi));
    return d;
}

// ---------------- prep: weights -> fp16 ---------------------------------------
__global__ void k_prep(const float* __restrict__ W_in, const float* __restrict__ conv_w,
                       const float* __restrict__ C) {
    int idx = blockIdx.x * blockDim.x + threadIdx.x;
    if (idx < ST*IND) {
        g_wt[idx] = __float2half_rn(W_in[idx]);
    }
    if (idx < ST*3*ST) {
        int n = idx / (3*ST);
        int rem = idx % (3*ST);
        int tap = rem / ST, i = rem % ST;
        g_wk[idx] = __float2half_rn(conv_w[((size_t)n*ST + i)*3 + tap]);
    }
    if (idx < OD*ST) {
        int n = idx / ST, k = idx % ST;
        g_ct[idx] = __float2half_rn(C[(size_t)k*OD + n]);
    }
    if (idx < ST) { g_sum[idx] = 0.f; g_sumsq[idx] = 0.f; }
}

// x -> fp16
__global__ __launch_bounds__(256)
void k_split(const float* __restrict__ x) {
    const size_t i = ((size_t)blockIdx.x * 256 + threadIdx.x) * 4;
    float4 v = *(const float4*)(x + i);
    __half2 h0 = __floats2half2_rn(v.x, v.y);
    __half2 h1 = __floats2half2_rn(v.z, v.w);
    uint2 hh; hh.x = *(uint32_t*)&h0; hh.y = *(uint32_t*)&h1;
    *(uint2*)(g_xh + i) = hh;
}

// ---------------- mma.sync helpers --------------------------------------------
__device__ __forceinline__ void mma16816(float* c, const uint32_t* a, const uint32_t* b) {
    asm volatile(
        "mma.sync.aligned.m16n8k16.row.col.f32.f16.f16.f32 "
        "{%0,%1,%2,%3}, {%4,%5,%6,%7}, {%8,%9}, {%0,%1,%2,%3};"
        : "+f"(c[0]), "+f"(c[1]), "+f"(c[2]), "+f"(c[3])
        : "r"(a[0]), "r"(a[1]), "r"(a[2]), "r"(a[3]), "r"(b[0]), "r"(b[1]));
}
__device__ __forceinline__ void ldsm4(uint32_t* r, uint32_t addr) {
    asm volatile("ldmatrix.sync.aligned.m8n8.x4.shared.b16 {%0,%1,%2,%3}, [%4];"
                 : "=r"(r[0]), "=r"(r[1]), "=r"(r[2]), "=r"(r[3]) : "r"(addr));
}
__device__ __forceinline__ void cpa16(uint32_t dst, const void* src, bool pred) {
    int sz = pred ? 16 : 0;
    asm volatile("cp.async.cg.shared.global [%0], [%1], 16, %2;"
                 :: "r"(dst), "l"(src), "r"(sz) : "memory");
}
#define CPA_COMMIT() asm volatile("cp.async.commit_group;" ::: "memory")

// ---------------- fp16 warp-MMA GEMM (single-term A) ---------------------------
#define SRS 72
#define TILE_HALFS (128*SRS)             // 18432 B
#define CHUNKH (2*TILE_HALFS)            // A, B
#define SMB_TOTAL (3*CHUNKH*2)           // 110592 B

__global__ __launch_bounds__(256, 2)
void k_tgemm(const __half* __restrict__ Ah, const __half* __restrict__ Bp,
             const float* __restrict__ bias, float* __restrict__ outf,
             __half* __restrict__ outh,
             int Kd, int N, int act, int convmode) {
    extern __shared__ __half smem[];
    const int t = threadIdx.x;
    const int w = t >> 5, lane = t & 31;
    const int wm = w >> 1, wn = w & 1;
    const int m0 = blockIdx.y * 128, n0 = blockIdx.x * 128;

    float acc[2][8][4];
#pragma unroll
    for (int i = 0; i < 2; i++)
#pragma unroll
        for (int j = 0; j < 8; j++)
#pragma unroll
            for (int q = 0; q < 4; q++) acc[i][j][q] = 0.f;

    const uint32_t smb = smem_u32(smem);
    const uint32_t aBase = smb +
        (uint32_t)(((wm*32 + (lane & 15)) * SRS + (lane >> 4) * 8) * 2);
    const uint32_t bBase = smb + TILE_HALFS*2 +
        (uint32_t)(((wn*64 + (lane & 7) + ((lane >> 4) & 1) * 8) * SRS
                    + ((lane >> 3) & 1) * 8) * 2);

    const int sr = t >> 3, sj = t & 7;
    const int nch = Kd >> 6;

    auto stage = [&](int c, int buf) {
        const int k0 = c << 6;
        __half* base = smem + buf * CHUNKH;
        __half* sAh = base;
        __half* sB  = base + TILE_HALFS;
        const int tap = convmode ? (k0 >> 9) : 0;
        const int kl0 = convmode ? (k0 & 511) : k0;
#pragma unroll
        for (int it = 0; it < 4; it++) {
            const int r = sr + it * 32;
            const uint32_t so = (uint32_t)((r * SRS + sj * 8) * 2);
            {
                const size_t goff = (size_t)(n0 + r) * Kd + k0 + sj * 8;
                cpa16(smem_u32(sB) + so, Bp + goff, true);
            }
            {
                const int rg = m0 + r;
                bool pred = true;
                size_t goff;
                if (convmode) {
                    const int tl = (rg & (Tz - 1)) + tap - 1;
                    pred = (tl >= 0) && (tl < Tz);
                    const int rs = pred ? (rg + tap - 1) : rg;
                    goff = (size_t)rs * ST + kl0 + sj * 8;
                } else {
                    goff = (size_t)rg * Kd + k0 + sj * 8;
                }
                cpa16(smem_u32(sAh) + so, Ah + goff, pred);
            }
        }
    };

    uint32_t fah[2][4], fb[4][4];

    stage(0, 0);
    CPA_COMMIT();
    if (nch > 1) { stage(1, 1); CPA_COMMIT(); }

    for (int c = 0; c < nch; c++) {
        if (c < nch - 1) asm volatile("cp.async.wait_group 1;" ::: "memory");
        else             asm volatile("cp.async.wait_group 0;" ::: "memory");
        __syncthreads();
        if (c + 2 < nch) { stage(c + 2, (c + 2) % 3); CPA_COMMIT(); }

        const uint32_t boff = (uint32_t)((c % 3) * CHUNKH * 2);
#pragma unroll
        for (int ks = 0; ks < 4; ks++) {
            const uint32_t koff = boff + (uint32_t)(ks * 32);
#pragma unroll
            for (int mi = 0; mi < 2; mi++)
                ldsm4(fah[mi], aBase + (uint32_t)(mi * 16 * SRS * 2) + koff);
#pragma unroll
            for (int nb = 0; nb < 4; nb++)
                ldsm4(fb[nb], bBase + (uint32_t)(nb * 16 * SRS * 2) + koff);
#pragma unroll
            for (int mi = 0; mi < 2; mi++)
#pragma unroll
                for (int ni = 0; ni < 8; ni++)
                    mma16816(acc[mi][ni], fah[mi], &fb[ni >> 1][(ni & 1) * 2]);
        }
    }

    const int g = lane >> 2, tg = lane & 3;
#pragma unroll
    for (int mi = 0; mi < 2; mi++) {
#pragma unroll
        for (int ni = 0; ni < 8; ni++) {
            const int col = n0 + wn*64 + ni*8 + tg*2;
            const float b0 = bias ? bias[col]     : 0.f;
            const float b1 = bias ? bias[col + 1] : 0.f;
#pragma unroll
            for (int half = 0; half < 2; half++) {
                const int row = m0 + wm*32 + mi*16 + g + half*8;
                float v0 = acc[mi][ni][half*2+0] + b0;
                float v1 = acc[mi][ni][half*2+1] + b1;
                if (act == 1) {
                    v0 = v0 / (1.f + expf(-v0));
                    v1 = v1 / (1.f + expf(-v1));
                }
                if (outf) {
                    float2 f2; f2.x = v0; f2.y = v1;
                    *(float2*)(outf + (size_t)row * N + col) = f2;
                }
                if (outh) {
                    __half2 h2 = __floats2half2_rn(v0, v1);
                    *(__half2*)(outh + (size_t)row * N + col) = h2;
                }
            }
        }
    }
}

// ---------------- BN stats -----------------------------------------------------
__global__ __launch_bounds__(512)
void k_stats() {
    const int n = threadIdx.x;
    const int rpc = M_ROWS / 512;
    const int r0 = blockIdx.x * rpc;
    float s1 = 0.f, s2 = 0.f;
    for (int r = 0; r < rpc; r++) {
        const size_t o = (size_t)(r0 + r) * ST + n;
        float v = __half2float(g_vch[o]);
        s1 += v; s2 += v * v;
    }
    atomicAdd(&g_sum[n], s1);
    atomicAdd(&g_sumsq[n], s2);
}

__global__ __launch_bounds__(512)
void k_finalize(const float* __restrict__ Bm, const float* __restrict__ bng,
                const float* __restrict__ bnb) {
    __shared__ float sc[ST], sh[ST];
    const int j = threadIdx.x;
    float mu  = g_sum[j]   * (1.f / M_ROWS);
    float var = g_sumsq[j] * (1.f / M_ROWS) - mu * mu;
    float inv = rsqrtf(var + EPSC);
    float s   = bng[j] * inv;
    sc[j] = s;
    sh[j] = bnb[j] - mu * s;
    __syncthreads();
    float ub = 0.f;
    for (int i = 0; i < ST; i++) {
        float bmv = Bm[(size_t)i * ST + j];
        g_bm[(size_t)j * ST + i] = __float2half_rn(sc[i] * bmv);
        ub += sh[i] * bmv;
    }
    g_ubias[j] = ub;
}

// ---------------- cluster recurrence: folded LN, 1 sync + 1 barrier/step -------
// R14 layout (sbuf [2][chain][512], coalesced broadcasts); pbuf holds UNCOMBINED
// per-warp (s1,s2): [2][rank(8)][16] -> leaders push 8B packets, no 2nd sync.
#define PRED_STRIDE 260
#define RC_OFF_SBUF 32768                            // [2][4][512] = 4096
#define RC_OFF_PBUF (RC_OFF_SBUF + 4096)             // [2][8][16]  = 256
#define RC_OFF_PRED (RC_OFF_PBUF + 256)              // [32][260]
#define RC_OFF_CS   (RC_OFF_PRED + 32*PRED_STRIDE)   // colsum [64]
#define RC_OFF_CB   (RC_OFF_CS + 64)                 // cbias  [64]
#define RC_SMEM_FLOATS (RC_OFF_CB + 64 + 8)
__global__ __launch_bounds__(512, 1) __cluster_dims__(8, 1, 1)
void k_recur(const float* __restrict__ A, const float* __restrict__ lng,
             const float* __restrict__ lnb) {
    extern __shared__ float sm[];
    float* Atile  = sm;                  // [512][64] = gamma[i]*A[i][jg0+j]
    float* sbuf   = sm + RC_OFF_SBUF;
    float* pbuf   = sm + RC_OFF_PBUF;
    float* pred   = sm + RC_OFF_PRED;
    float* colsum = sm + RC_OFF_CS;
    float* cbias  = sm + RC_OFF_CB;

    const int t    = threadIdx.x;
    const int rank = blockIdx.x;
    const int grp  = blockIdx.y;
    const int jg0  = rank * 64;

    for (int idx = t; idx < 512 * 16; idx += 512) {
        int i  = idx >> 4;
        int jv = (idx & 15) << 2;
        float gi = lng[i];
        float4 a = *(const float4*)(A + (size_t)i*ST + jg0 + jv);
        a.x *= gi; a.y *= gi; a.z *= gi; a.w *= gi;
        *(float4*)&Atile[i*64 + jv] = a;
    }
    for (int idx = t; idx < 4*512; idx += 512) sbuf[idx] = 0.f;
    __syncthreads();
    if (t < 64) {
        float cs = 0.f;
        for (int i = 0; i < 512; i++) cs += Atile[i*64 + t];
        colsum[t] = cs;
    } else if (t < 128) {
        const int jj2 = t - 64;
        float cb = 0.f;
        for (int i = 0; i < 512; i++)
            cb += lnb[i] * A[(size_t)i*ST + jg0 + jj2];
        cbias[jj2] = cb;
    }

    const int ip = t >> 4;
    const int jq = t & 15;
    const int c2 = t >> 6;         // chain (t<256)
    const int jj = t & 63;
    const int wid = t >> 5;        // warp (0..7 for t<256)

    float gj = 0.f, bj = 0.f;
    size_t urow0 = 0;
    if (t < 256) {
        gj = lng[jg0 + jj];
        bj = lnb[jg0 + jj];
        const int chain = grp * 4 + c2;
        urow0 = (size_t)chain * Tz * ST + jg0 + jj;
    }

    const uint32_t sb_base = smem_u32(sbuf);
    const uint32_t pb_base = smem_u32(pbuf);

    __syncthreads();
    asm volatile("barrier.cluster.arrive.aligned;\n" ::: "memory");
    asm volatile("barrier.cluster.wait.aligned;\n" ::: "memory");

    int p = 0;
    float uval  = (t < 256) ? g_u[urow0] : 0.f;
    float yprev = 0.f;

    for (int step = 0; step < Tz; step++) {
        // ---- matvec (R14 form: 4-chain A-reuse, scalar FFMA) ---------------
        const float* Arow = Atile + (ip*16)*64 + jq*4;
        const float* s0p = sbuf + (p*4 + 0)*512 + ip*16;
        const float* s1p = s0p + 512;
        const float* s2p = s1p + 512;
        const float* s3p = s2p + 512;
        float4 a0 = make_float4(0,0,0,0), a1 = a0, a2 = a0, a3 = a0;
#pragma unroll
        for (int ii = 0; ii < 16; ii += 4) {
            float4 sA = *(const float4*)(s0p + ii);
            float4 sB_ = *(const float4*)(s1p + ii);
            float4 sC = *(const float4*)(s2p + ii);
            float4 sD = *(const float4*)(s3p + ii);
#pragma unroll
            for (int q2 = 0; q2 < 4; q2++) {
                float4 av = *(const float4*)(Arow + (ii + q2) * 64);
                const float w0 = (&sA.x)[q2], w1 = (&sB_.x)[q2];
                const float w2 = (&sC.x)[q2], w3 = (&sD.x)[q2];
                a0.x = fmaf(w0, av.x, a0.x); a0.y = fmaf(w0, av.y, a0.y);
                a0.z = fmaf(w0, av.z, a0.z); a0.w = fmaf(w0, av.w, a0.w);
                a1.x = fmaf(w1, av.x, a1.x); a1.y = fmaf(w1, av.y, a1.y);
                a1.z = fmaf(w1, av.z, a1.z); a1.w = fmaf(w1, av.w, a1.w);
                a2.x = fmaf(w2, av.x, a2.x); a2.y = fmaf(w2, av.y, a2.y);
                a2.z = fmaf(w2, av.z, a2.z); a2.w = fmaf(w2, av.w, a2.w);
                a3.x = fmaf(w3, av.x, a3.x); a3.y = fmaf(w3, av.y, a3.y);
                a3.z = fmaf(w3, av.z, a3.z); a3.w = fmaf(w3, av.w, a3.w);
            }
        }
        {
            float* pr = pred + ip * PRED_STRIDE + jq * 4;
            *(float4*)(pr + 0*64) = a0;
            *(float4*)(pr + 1*64) = a1;
            *(float4*)(pr + 2*64) = a2;
            *(float4*)(pr + 3*64) = a3;
        }
        __syncthreads();

        // ---- finalize (t<256): stats of r_{t-1}, write s_{t-1}, r_t --------
        float ynew = 0.f;
        if (t < 256) {
            float alpha = 0.f, beta = 0.f, cw = 0.f;
            if (step > 0) {
                float q1 = 0.f, q2s = 0.f;
                const int w0 = c2 * 4;
#pragma unroll
                for (int r = 0; r < 8; r++) {
                    const float* pb = pbuf + p*128 + r*16 + w0;
                    q1  += pb[0] + pb[2];
                    q2s += pb[1] + pb[3];
                }
                const float mean = q1 * (1.f / ST);
                const float var  = q2s * (1.f / ST) - mean * mean;
                const float rstd = rsqrtf(var + EPSC);
                alpha = rstd; beta = -rstd * mean; cw = 1.f;
                const float sv = (yprev - mean) * rstd * gj + bj;
                g_sh[urow0 + (size_t)(step-1) * ST] = __float2half_rn(sv);
            }
            float acc = 0.f;
            const float* pr = pred + c2 * 64 + jj;
#pragma unroll 8
            for (int q = 0; q < 32; q++)
                acc += pr[q * PRED_STRIDE];
            ynew = fmaf(alpha, acc, fmaf(beta, colsum[jj], fmaf(cw, cbias[jj], uval)));

            // broadcast raw r_t (R14 coalesced addressing)
            {
                const uint32_t la = sb_base +
                    (uint32_t)(((((p^1)*4 + c2)*512) + jg0 + jj) * 4);
#pragma unroll
                for (int r = 0; r < 8; r++) {
                    uint32_t ra_;
                    asm volatile("mapa.shared::cluster.u32 %0, %1, %2;" : "=r"(ra_) : "r"(la), "r"(r));
                    asm volatile("st.shared::cluster.f32 [%0], %1;" :: "r"(ra_), "f"(ynew) : "memory");
                }
            }
            // warp partials: leaders push uncombined 8B packets (no 2nd sync)
            float s1 = ynew, s2 = ynew * ynew;
#pragma unroll
            for (int o = 16; o > 0; o >>= 1) {
                s1 += __shfl_xor_sync(0xffffffffu, s1, o);
                s2 += __shfl_xor_sync(0xffffffffu, s2, o);
            }
            if ((t & 31) == 0) {
                double pv = pack2(s1, s2);
                const uint32_t la = pb_base +
                    (uint32_t)(((p^1)*128 + rank*16 + wid*2) * 4);
#pragma unroll
                for (int r = 0; r < 8; r++) {
                    uint32_t ra_;
                    asm volatile("mapa.shared::cluster.u32 %0, %1, %2;" : "=r"(ra_) : "r"(la), "r"(r));
                    asm volatile("st.shared::cluster.b64 [%0], %1;" :: "r"(ra_), "d"(pv) : "memory");
                }
            }
        }
        float unext = 0.f;
        if (t < 256 && step + 1 < Tz)
            unext = g_u[urow0 + (size_t)(step + 1) * ST];

        asm volatile("barrier.cluster.arrive.aligned;\n" ::: "memory");
        asm volatile("barrier.cluster.wait.aligned;\n" ::: "memory");

        yprev = ynew;
        uval  = unext;
        p ^= 1;
    }

    // tail: write s_{Tz-1}
    if (t < 256) {
        float q1 = 0.f, q2s = 0.f;
        const int w0 = c2 * 4;
#pragma unroll
        for (int r = 0; r < 8; r++) {
            const float* pb = pbuf + p*128 + r*16 + w0;
            q1  += pb[0] + pb[2];
            q2s += pb[1] + pb[3];
        }
        const float mean = q1 * (1.f / ST);
        const float var  = q2s * (1.f / ST) - mean * mean;
        const float rstd = rsqrtf(var + EPSC);
        const float sv = (yprev - mean) * rstd * gj + bj;
        g_sh[urow0 + (size_t)(Tz-1) * ST] = __float2half_rn(sv);
    }
}

// ---------------- launch ------------------------------------------------------
extern "C" void kernel_launch(void* const* d_in, const int* in_sizes, int n_in,
                              void* d_out, int out_size) {
    const float* x      = (const float*)d_in[0];
    const float* W_in   = (const float*)d_in[1];
    const float* b_in   = (const float*)d_in[2];
    const float* conv_w = (const float*)d_in[3];
    const float* conv_b = (const float*)d_in[4];
    const float* bng    = (const float*)d_in[5];
    const float* bnb    = (const float*)d_in[6];
    const float* lng    = (const float*)d_in[7];
    const float* lnb    = (const float*)d_in[8];
    const float* A      = (const float*)d_in[9];
    const float* Bm     = (const float*)d_in[10];
    const float* C      = (const float*)d_in[11];
    float* out = (float*)d_out;

    void *p_xh, *p_vh, *p_vch, *p_u, *p_sh;
    void *p_wt, *p_wk, *p_bm, *p_ct, *p_ub;
    cudaGetSymbolAddress(&p_xh,  g_xh);
    cudaGetSymbolAddress(&p_vh,  g_vh);
    cudaGetSymbolAddress(&p_vch, g_vch);
    cudaGetSymbolAddress(&p_u,   g_u);
    cudaGetSymbolAddress(&p_sh,  g_sh);
    cudaGetSymbolAddress(&p_wt,  g_wt);  cudaGetSymbolAddress(&p_wk,  g_wk);
    cudaGetSymbolAddress(&p_bm,  g_bm);  cudaGetSymbolAddress(&p_ct,  g_ct);
    cudaGetSymbolAddress(&p_ub,  g_ubias);

    cudaFuncSetAttribute(k_tgemm, cudaFuncAttributeMaxDynamicSharedMemorySize, SMB_TOTAL);
    cudaFuncSetAttribute(k_recur, cudaFuncAttributeMaxDynamicSharedMemorySize,
                         RC_SMEM_FLOATS * 4);

    // 1) weights + x -> fp16
    k_prep<<<1536, 512>>>(W_in, conv_w, C);
    k_split<<<(M_ROWS*IND)/1024, 256>>>(x);
    // 2) v = silu(x @ W_in^T + b_in) -> fp16
    k_tgemm<<<dim3(4, 1024), 256, SMB_TOTAL>>>(
        (const __half*)p_xh, (const __half*)p_wt,
        b_in, nullptr, (__half*)p_vh, IND, ST, 1, 0);
    // 3) vc = conv1d(v) + conv_b -> fp16
    k_tgemm<<<dim3(4, 1024), 256, SMB_TOTAL>>>(
        (const __half*)p_vh, (const __half*)p_wk,
        conv_b, nullptr, (__half*)p_vch, 3*ST, ST, 0, 1);
    // 4) BN stats
    k_stats<<<512, 512>>>();
    // 5) fold BN into Bm
    k_finalize<<<1, 512>>>(Bm, bng, bnb);
    // 6) u = vc @ Bm2 + ubias -> fp32
    k_tgemm<<<dim3(4, 1024), 256, SMB_TOTAL>>>(
        (const __half*)p_vch, (const __half*)p_bm,
        (const float*)p_ub, (float*)p_u, nullptr, ST, ST, 0, 0);
    // 7) recurrence -> fp16 states
    k_recur<<<dim3(8, 16), 512, RC_SMEM_FLOATS * 4>>>(A, lng, lnb);
    // 8) y = S @ C
    k_tgemm<<<dim3(2, 1024), 256, SMB_TOTAL>>>(
        (const __half*)p_sh, (const __half*)p_ct,
        nullptr, out, nullptr, ST, OD, 0, 0);
}